// round 15
// baseline (speedup 1.0000x reference)
#include <cuda_runtime.h>
#include <cuda_bf16.h>
#include <cuda_fp16.h>
#include <math.h>
#include <stdint.h>

// Problem dims (fixed)
#define B_  8
#define T_  2048
#define C_  768
#define H_  64
#define NROWS (B_ * T_)
#define SCALE 0.036084391824351615f      // 1/sqrt(768)
#define SCALE_L2E 0.05205953318987122f   // SCALE * log2(e)

typedef unsigned long long u64;
typedef uint32_t u32;

// W pre-split (fp16 hi/lo), concatenated [C][192] = [Wk | Wq*S | Wv].
// q/k/v stored single fp16 (q pre-scaled by SCALE*log2e via Wq).
__device__ __half g_whi[C_ * 192];
__device__ __half g_wlo[C_ * 192];
__device__ __half g_q16[NROWS * H_];
__device__ __half g_k16[NROWS * H_];
__device__ __half g_v16[NROWS * H_];
// KV-split partials (fp32)
__device__ float g_on[2 * NROWS * H_];   // 8 MB
__device__ float g_rs[2 * NROWS];
// monotonic arrival counter for qkv's cooperative W-split barrier (never reset)
__device__ u32 g_wcnt;

// ---- helpers ----
__device__ __forceinline__ u32 smem_u32(const void* p) {
    u32 a; asm("{ .reg .u64 t; cvta.to.shared.u64 t, %1; cvt.u32.u64 %0, t; }" : "=r"(a) : "l"(p));
    return a;
}
__device__ __forceinline__ u32 pack_f16(float e0, float e1) {
    u32 d; asm("cvt.rn.f16x2.f32 %0, %2, %1;" : "=r"(d) : "f"(e0), "f"(e1)); return d;
}
__device__ __forceinline__ u32 ex2h2(u32 a) {
    u32 d; asm("ex2.approx.f16x2 %0, %1;" : "=r"(d) : "r"(a)); return d;
}
__device__ __forceinline__ void mma_f16(float c[4], u32 a0, u32 a1, u32 a2, u32 a3, u32 b0, u32 b1) {
    asm volatile(
        "mma.sync.aligned.m16n8k16.row.col.f32.f16.f16.f32 "
        "{%0,%1,%2,%3}, {%4,%5,%6,%7}, {%8,%9}, {%0,%1,%2,%3};"
        : "+f"(c[0]), "+f"(c[1]), "+f"(c[2]), "+f"(c[3])
        : "r"(a0), "r"(a1), "r"(a2), "r"(a3), "r"(b0), "r"(b1));
}
__device__ __forceinline__ void mma4h(float c[4], const u32 a[4], u32 b0, u32 b1) {
    mma_f16(c, a[0], a[1], a[2], a[3], b0, b1);
}
__device__ __forceinline__ void ldm4(u32 r[4], u32 addr) {
    asm volatile("ldmatrix.sync.aligned.m8n8.x4.shared.b16 {%0,%1,%2,%3}, [%4];"
        : "=r"(r[0]), "=r"(r[1]), "=r"(r[2]), "=r"(r[3]) : "r"(addr));
}
__device__ __forceinline__ void ldm4t(u32 r[4], u32 addr) {
    asm volatile("ldmatrix.sync.aligned.m8n8.x4.trans.shared.b16 {%0,%1,%2,%3}, [%4];"
        : "=r"(r[0]), "=r"(r[1]), "=r"(r[2]), "=r"(r[3]) : "r"(addr));
}
#define CP16(dst, src) asm volatile("cp.async.cg.shared.global [%0], [%1], 16;" :: "r"(dst), "l"(src) : "memory")
#define CP_COMMIT()    asm volatile("cp.async.commit_group;" ::: "memory")
#define CP_WAIT0()     asm volatile("cp.async.wait_group 0;" ::: "memory")

// ============================================================================
// Kernel 1: QKV projection on HMMA, fp16 2-term, software-pipelined.
// Cooperative W-split prologue (grid=128, all CTAs resident -> safe grid
// barrier via monotonic counter). Replaces the separate w_split kernel.
// ============================================================================
#define XR 144
#define WR 400
#define QB_X   0
#define QB_WHI 18432
#define QB_WLO 44032
#define QBUF   69632
#define QKV_SMEM (2 * QBUF)   // 139264

__device__ __forceinline__ void qkv_issue_w(u32 base, int k0, int tid)
{
    #pragma unroll
    for (int i = 0; i < 12; i++) {
        int idx = tid + i * 256;
        int a = idx >= 1536;
        int j = a ? idx - 1536 : idx;
        int r = j / 24, ch = j - r * 24;
        const char* src = (const char*)(a ? g_wlo : g_whi)
                        + ((size_t)(k0 + r) * 192 + ch * 8) * 2;
        CP16(base + (a ? QB_WLO : QB_WHI) + r * WR + ch * 16, src);
    }
}

__global__ __launch_bounds__(256, 1) void qkv_mma_kernel(
    const float* __restrict__ x,
    const float* __restrict__ Wk,
    const float* __restrict__ Wq,
    const float* __restrict__ Wv)
{
    extern __shared__ char smem[];
    const u32 sb = smem_u32(smem);
    const int tid = threadIdx.x;
    const int wid = tid >> 5;
    const int l   = tid & 31;
    const int g   = l >> 2;
    const int tg  = l & 3;
    const int row0 = blockIdx.x * 128;

    // ---- cooperative W split: this CTA's 1/128th slice (1152 elements) ----
    {
        const int base = blockIdx.x * (C_ * 192 / 128);   // 1152 per CTA
        for (int i = tid; i < C_ * 192 / 128; i += 256) {
            int idx = base + i;
            int k = idx / 192, c = idx % 192;
            float v;
            if (c < 64)       v = Wk[k * 64 + c];
            else if (c < 128) v = Wq[k * 64 + (c - 64)] * SCALE_L2E;
            else              v = Wv[k * 64 + (c - 128)];
            __half h = __float2half_rn(v);
            g_whi[idx] = h;
            g_wlo[idx] = __float2half_rn(v - __half2float(h));
        }
        __threadfence();
        __syncthreads();
        if (tid == 0) {
            u32 a = atomicAdd(&g_wcnt, 1u) + 1u;
            u32 target = ((a + 127u) >> 7) << 7;   // end of this replay's group
            while (*(volatile u32*)&g_wcnt < target) { }
        }
        __syncthreads();
        __threadfence();   // acquire: other CTAs' W writes now visible
    }

    float c[12][2][4];
    #pragma unroll
    for (int nt = 0; nt < 12; nt++)
        #pragma unroll
        for (int s = 0; s < 2; s++)
            #pragma unroll
            for (int j = 0; j < 4; j++) c[nt][s][j] = 0.0f;

    qkv_issue_w(sb, 0, tid);
    CP_COMMIT();
    #pragma unroll
    for (int i = 0; i < 16; i++) {
        int idx = tid + i * 256;
        int r = idx >> 5, cp = (idx & 31) * 2;
        float2 v = *(const float2*)&x[(size_t)(row0 + r) * C_ + cp];
        *(u32*)(smem + QB_X + r * XR + cp * 2) = pack_f16(v.x, v.y);
    }

    for (int it = 0; it < 12; it++) {
        const int buf = it & 1;
        const u32 bb = sb + buf * QBUF;
        CP_WAIT0();
        __syncthreads();

        float2 xr[16];
        if (it < 11) {
            const int k0n = (it + 1) * 64;
            #pragma unroll
            for (int i = 0; i < 16; i++) {
                int idx = tid + i * 256;
                int r = idx >> 5, cp = (idx & 31) * 2;
                xr[i] = *(const float2*)&x[(size_t)(row0 + r) * C_ + k0n + cp];
            }
            qkv_issue_w(sb + (buf ^ 1) * QBUF, k0n, tid);
            CP_COMMIT();
        }

        #pragma unroll
        for (int kk = 0; kk < 4; kk++) {
            u32 a[4];
            ldm4(a, bb + QB_X
                 + (u32)((wid * 16 + (l & 15)) * XR + kk * 32 + ((l >> 4) << 4)));
            u32 brow = bb
                     + (u32)((kk * 16 + (l & 7) + (((l >> 3) & 1) << 3)) * WR + ((l >> 4) << 4));
            #pragma unroll
            for (int nt = 0; nt < 12; nt++) {
                u32 bh[4], bl[4];
                ldm4t(bh, brow + QB_WHI + nt * 32);
                mma4h(c[nt][0], a, bh[0], bh[1]);
                mma4h(c[nt][1], a, bh[2], bh[3]);
                ldm4t(bl, brow + QB_WLO + nt * 32);
                mma4h(c[nt][0], a, bl[0], bl[1]);
                mma4h(c[nt][1], a, bl[2], bl[3]);
            }
        }

        if (it < 11) {
            #pragma unroll
            for (int i = 0; i < 16; i++) {
                int idx = tid + i * 256;
                int r = idx >> 5, cp = (idx & 31) * 2;
                *(u32*)(smem + (buf ^ 1) * QBUF + QB_X + r * XR + cp * 2) =
                    pack_f16(xr[i].x, xr[i].y);
            }
        }
    }

    const int r0 = row0 + wid * 16 + g;
    const int r1 = r0 + 8;
    #pragma unroll
    for (int nt = 0; nt < 12; nt++) {
        int mat = nt >> 2;
        __half* dst = (mat == 0) ? g_k16 : (mat == 1) ? g_q16 : g_v16;
        int cm = (nt & 3) * 16 + 2 * tg;
        #pragma unroll
        for (int s = 0; s < 2; s++) {
            int col = cm + s * 8;
            *(u32*)&dst[(size_t)r0 * H_ + col] = pack_f16(c[nt][s][0], c[nt][s][1]);
            *(u32*)&dst[(size_t)r1 * H_ + col] = pack_f16(c[nt][s][2], c[nt][s][3]);
        }
    }
}

// ============================================================================
// Kernel 2: flash attention, all-fp16, KV-SPLIT x2 + 2 CTAs/SM (round-11 champion).
// ============================================================================
#define KROW 144
#define TILE_B (128 * KROW)        // 18432
#define BUF_B  (2 * TILE_B)        // k + v
#define ATTN_SMEM (2 * BUF_B)      // 73728 per CTA

__device__ __forceinline__ void stage_tile(u32 sb, int buf, int kbase, int tid)
{
    const u32 base = sb + buf * BUF_B;
    #pragma unroll
    for (int i = 0; i < 8; i++) {
        int idx = tid + i * 256;
        int arr = idx >> 10, j = idx & 1023;
        int r = j >> 3, ch = j & 7;
        const char* src = (const char*)(arr == 0 ? g_k16 : g_v16)
                        + ((size_t)(kbase + r) * H_ + ch * 8) * 2;
        CP16(base + arr * TILE_B + r * KROW + ch * 16, src);
    }
}

__global__ __launch_bounds__(256, 2) void attn_mma_kernel()
{
    extern __shared__ char smem[];
    const u32 sb = smem_u32(smem);

    const int tid = threadIdx.x;
    const int wid = tid >> 5;
    const int l   = tid & 31;
    const int g   = l >> 2;
    const int tg  = l & 3;

    const int split = blockIdx.x & 1;
    const int tile  = (blockIdx.x >> 1) & 15;
    const int b     = blockIdx.x >> 5;
    const int qbase  = b * T_ + tile * 128;
    const int kstart = b * T_ + split * (T_ / 2);
    const int r0 = qbase + wid * 16 + g;
    const int r1 = r0 + 8;

    u32 aQ[4][4];
    #pragma unroll
    for (int kk = 0; kk < 4; kk++) {
        int cb = kk * 16 + 2 * tg;
        aQ[kk][0] = *(const u32*)&g_q16[(size_t)r0 * H_ + cb];
        aQ[kk][1] = *(const u32*)&g_q16[(size_t)r1 * H_ + cb];
        aQ[kk][2] = *(const u32*)&g_q16[(size_t)r0 * H_ + cb + 8];
        aQ[kk][3] = *(const u32*)&g_q16[(size_t)r1 * H_ + cb + 8];
    }

    const u32 kRowOff = (u32)(((l & 7) + ((l >> 4) << 3)) * KROW + (((l >> 3) & 1) << 4));
    const u32 vRowOff = (u32)(((l & 7) + (((l >> 3) & 1) << 3)) * KROW + ((l >> 4) << 4));

    const u32 bOnes = (g == 0) ? 0x3C003C00u : 0u;

    float oc[8][4];
    #pragma unroll
    for (int i = 0; i < 8; i++)
        #pragma unroll
        for (int j = 0; j < 4; j++) oc[i][j] = 0.0f;
    float ocrs[4] = {0.0f, 0.0f, 0.0f, 0.0f};

    stage_tile(sb, 0, kstart, tid);
    CP_COMMIT();

    const int NT = (T_ / 2) / 128;   // 8
    for (int t = 0; t < NT; t++) {
        CP_WAIT0();
        __syncthreads();
        const int buf = t & 1;
        if (t + 1 < NT) {
            stage_tile(sb, buf ^ 1, kstart + (t + 1) * 128, tid);
            CP_COMMIT();
        }
        const u32 kh = sb + buf * BUF_B;
        const u32 vh = kh + TILE_B;

        #pragma unroll
        for (int kg = 0; kg < 8; kg++) {
            float s0[4] = {0.f, 0.f, 0.f, 0.f};
            float s1[4] = {0.f, 0.f, 0.f, 0.f};
            #pragma unroll
            for (int ks = 0; ks < 4; ks++) {
                u32 kb[4];
                ldm4(kb, kh + (u32)(kg * 16 * KROW + ks * 32) + kRowOff);
                mma4h(s0, aQ[ks], kb[0], kb[1]);
                mma4h(s1, aQ[ks], kb[2], kb[3]);
            }
            u32 ph[4];
            ph[0] = ex2h2(pack_f16(s0[0], s0[1]));
            ph[1] = ex2h2(pack_f16(s0[2], s0[3]));
            ph[2] = ex2h2(pack_f16(s1[0], s1[1]));
            ph[3] = ex2h2(pack_f16(s1[2], s1[3]));
            mma4h(ocrs, ph, bOnes, bOnes);
            #pragma unroll
            for (int np = 0; np < 4; np++) {
                u32 vb[4];
                ldm4t(vb, vh + (u32)(kg * 16 * KROW + np * 32) + vRowOff);
                mma4h(oc[2*np],   ph, vb[0], vb[1]);
                mma4h(oc[2*np+1], ph, vb[2], vb[3]);
            }
        }
    }

    // ---- epilogue: write unnormalized numerator + rowsum ----
    float* on = g_on + (size_t)split * (NROWS * H_);
    if (tg == 0) {
        g_rs[split * NROWS + r0] = ocrs[0];
        g_rs[split * NROWS + r1] = ocrs[2];
    }
    #pragma unroll
    for (int nt = 0; nt < 8; nt++) {
        int col = nt * 8 + 2 * tg;
        *(float2*)&on[(size_t)r0 * H_ + col] = make_float2(oc[nt][0], oc[nt][1]);
        *(float2*)&on[(size_t)r1 * H_ + col] = make_float2(oc[nt][2], oc[nt][3]);
    }
}

// ============================================================================
// Kernel 3: combine splits: out = (n0 + n1) / (r0 + r1)
// ============================================================================
__global__ void combine_kernel(float* __restrict__ out)
{
    int idx = blockIdx.x * 256 + threadIdx.x;        // float4 index, 262144 total
    int row = idx >> 4;                               // 16 float4 per row
    float inv = 1.0f / (g_rs[row] + g_rs[NROWS + row]);
    float4 a = ((const float4*)g_on)[idx];
    float4 c = ((const float4*)(g_on + (size_t)NROWS * H_))[idx];
    ((float4*)out)[idx] = make_float4((a.x + c.x) * inv, (a.y + c.y) * inv,
                                      (a.z + c.z) * inv, (a.w + c.w) * inv);
}

// ============================================================================
extern "C" void kernel_launch(void* const* d_in, const int* in_sizes, int n_in,
                              void* d_out, int out_size)
{
    const float* x  = (const float*)d_in[0];
    const float* Wk = (const float*)d_in[1];
    const float* Wq = (const float*)d_in[2];
    const float* Wv = (const float*)d_in[3];
    float* out = (float*)d_out;

    cudaFuncSetAttribute(qkv_mma_kernel,
                         cudaFuncAttributeMaxDynamicSharedMemorySize, QKV_SMEM);
    cudaFuncSetAttribute(attn_mma_kernel,
                         cudaFuncAttributeMaxDynamicSharedMemorySize, ATTN_SMEM);

    qkv_mma_kernel<<<NROWS / 128, 256, QKV_SMEM>>>(x, Wk, Wq, Wv);
    attn_mma_kernel<<<B_ * (T_ / 128) * 2, 256, ATTN_SMEM>>>();
    combine_kernel<<<NROWS * H_ / 4 / 256, 256>>>(out);
}

// round 16
// speedup vs baseline: 1.2473x; 1.2473x over previous
#include <cuda_runtime.h>
#include <cuda_bf16.h>
#include <cuda_fp16.h>
#include <math.h>
#include <stdint.h>

// Problem dims (fixed)
#define B_  8
#define T_  2048
#define C_  768
#define H_  64
#define NROWS (B_ * T_)
#define SCALE 0.036084391824351615f      // 1/sqrt(768)
#define SCALE_L2E 0.05205953318987122f   // SCALE * log2(e)

typedef unsigned long long u64;
typedef uint32_t u32;

// W single fp16, concatenated [C][192] = [Wk | Wq*S | Wv].
// q/k/v stored single fp16 (q pre-scaled by SCALE*log2e via Wq).
__device__ __half g_w16[C_ * 192];
__device__ __half g_q16[NROWS * H_];
__device__ __half g_k16[NROWS * H_];
__device__ __half g_v16[NROWS * H_];
// KV-split partials (fp32)
__device__ float g_on[2 * NROWS * H_];   // 8 MB
__device__ float g_rs[2 * NROWS];

// ---- helpers ----
__device__ __forceinline__ u32 smem_u32(const void* p) {
    u32 a; asm("{ .reg .u64 t; cvta.to.shared.u64 t, %1; cvt.u32.u64 %0, t; }" : "=r"(a) : "l"(p));
    return a;
}
__device__ __forceinline__ u32 pack_f16(float e0, float e1) {
    u32 d; asm("cvt.rn.f16x2.f32 %0, %2, %1;" : "=r"(d) : "f"(e0), "f"(e1)); return d;
}
__device__ __forceinline__ u32 ex2h2(u32 a) {
    u32 d; asm("ex2.approx.f16x2 %0, %1;" : "=r"(d) : "r"(a)); return d;
}
__device__ __forceinline__ void mma_f16(float c[4], u32 a0, u32 a1, u32 a2, u32 a3, u32 b0, u32 b1) {
    asm volatile(
        "mma.sync.aligned.m16n8k16.row.col.f32.f16.f16.f32 "
        "{%0,%1,%2,%3}, {%4,%5,%6,%7}, {%8,%9}, {%0,%1,%2,%3};"
        : "+f"(c[0]), "+f"(c[1]), "+f"(c[2]), "+f"(c[3])
        : "r"(a0), "r"(a1), "r"(a2), "r"(a3), "r"(b0), "r"(b1));
}
__device__ __forceinline__ void mma4h(float c[4], const u32 a[4], u32 b0, u32 b1) {
    mma_f16(c, a[0], a[1], a[2], a[3], b0, b1);
}
__device__ __forceinline__ void ldm4(u32 r[4], u32 addr) {
    asm volatile("ldmatrix.sync.aligned.m8n8.x4.shared.b16 {%0,%1,%2,%3}, [%4];"
        : "=r"(r[0]), "=r"(r[1]), "=r"(r[2]), "=r"(r[3]) : "r"(addr));
}
__device__ __forceinline__ void ldm4t(u32 r[4], u32 addr) {
    asm volatile("ldmatrix.sync.aligned.m8n8.x4.trans.shared.b16 {%0,%1,%2,%3}, [%4];"
        : "=r"(r[0]), "=r"(r[1]), "=r"(r[2]), "=r"(r[3]) : "r"(addr));
}
#define CP16(dst, src) asm volatile("cp.async.cg.shared.global [%0], [%1], 16;" :: "r"(dst), "l"(src) : "memory")
#define CP_COMMIT()    asm volatile("cp.async.commit_group;" ::: "memory")
#define CP_WAIT0()     asm volatile("cp.async.wait_group 0;" ::: "memory")

// ============================================================================
// Kernel 0: convert W to single fp16, concatenated [C][192] = [Wk | Wq*S | Wv]
// ============================================================================
__global__ void w_cvt_kernel(const float* __restrict__ Wk,
                             const float* __restrict__ Wq,
                             const float* __restrict__ Wv)
{
    int base = (blockIdx.x * 256 + threadIdx.x) * 4;
    #pragma unroll
    for (int j = 0; j < 4; j++) {
        int idx = base + j;
        if (idx >= C_ * 192) return;
        int k = idx / 192, c = idx % 192;
        float v;
        if (c < 64)       v = Wk[k * 64 + c];
        else if (c < 128) v = Wq[k * 64 + (c - 64)] * SCALE_L2E;
        else              v = Wv[k * 64 + (c - 128)];
        g_w16[idx] = __float2half_rn(v);
    }
}

// ============================================================================
// Kernel 1: QKV projection on HMMA, fp16 1-term (x single, W single),
// software-pipelined ping-pong buffers. mma count halved vs round 11.
// ============================================================================
#define XR 144     // x smem row stride bytes
#define WR 400     // W smem row stride bytes (384 data + 16 pad)
#define QB_X   0
#define QB_W   18432
#define QBUF   44032
#define QKV_SMEM (2 * QBUF)   // 88064

__device__ __forceinline__ void qkv_issue_w(u32 base, int k0, int tid)
{
    // 64 rows x 24 16B-chunks = 1536 cp.async over 256 threads
    #pragma unroll
    for (int i = 0; i < 6; i++) {
        int j = tid + i * 256;
        int r = j / 24, ch = j - r * 24;
        const char* src = (const char*)g_w16 + ((size_t)(k0 + r) * 192 + ch * 8) * 2;
        CP16(base + QB_W + r * WR + ch * 16, src);
    }
}

__global__ __launch_bounds__(256, 1) void qkv_mma_kernel(const float* __restrict__ x)
{
    extern __shared__ char smem[];
    const u32 sb = smem_u32(smem);
    const int tid = threadIdx.x;
    const int wid = tid >> 5;
    const int l   = tid & 31;
    const int g   = l >> 2;
    const int tg  = l & 3;
    const int row0 = blockIdx.x * 128;

    float c[12][2][4];
    #pragma unroll
    for (int nt = 0; nt < 12; nt++)
        #pragma unroll
        for (int s = 0; s < 2; s++)
            #pragma unroll
            for (int j = 0; j < 4; j++) c[nt][s][j] = 0.0f;

    qkv_issue_w(sb, 0, tid);
    CP_COMMIT();
    #pragma unroll
    for (int i = 0; i < 16; i++) {
        int idx = tid + i * 256;
        int r = idx >> 5, cp = (idx & 31) * 2;
        float2 v = *(const float2*)&x[(size_t)(row0 + r) * C_ + cp];
        *(u32*)(smem + QB_X + r * XR + cp * 2) = pack_f16(v.x, v.y);
    }

    for (int it = 0; it < 12; it++) {
        const int buf = it & 1;
        const u32 bb = sb + buf * QBUF;
        CP_WAIT0();
        __syncthreads();

        float2 xr[16];
        if (it < 11) {
            const int k0n = (it + 1) * 64;
            #pragma unroll
            for (int i = 0; i < 16; i++) {
                int idx = tid + i * 256;
                int r = idx >> 5, cp = (idx & 31) * 2;
                xr[i] = *(const float2*)&x[(size_t)(row0 + r) * C_ + k0n + cp];
            }
            qkv_issue_w(sb + (buf ^ 1) * QBUF, k0n, tid);
            CP_COMMIT();
        }

        #pragma unroll
        for (int kk = 0; kk < 4; kk++) {
            u32 a[4];
            ldm4(a, bb + QB_X
                 + (u32)((wid * 16 + (l & 15)) * XR + kk * 32 + ((l >> 4) << 4)));
            u32 brow = bb
                     + (u32)((kk * 16 + (l & 7) + (((l >> 3) & 1) << 3)) * WR + ((l >> 4) << 4));
            #pragma unroll
            for (int nt = 0; nt < 12; nt++) {
                u32 bh[4];
                ldm4t(bh, brow + QB_W + nt * 32);
                mma4h(c[nt][0], a, bh[0], bh[1]);
                mma4h(c[nt][1], a, bh[2], bh[3]);
            }
        }

        if (it < 11) {
            #pragma unroll
            for (int i = 0; i < 16; i++) {
                int idx = tid + i * 256;
                int r = idx >> 5, cp = (idx & 31) * 2;
                *(u32*)(smem + (buf ^ 1) * QBUF + QB_X + r * XR + cp * 2) =
                    pack_f16(xr[i].x, xr[i].y);
            }
        }
    }

    // ---- epilogue: write single fp16 k/q/v ----
    const int r0 = row0 + wid * 16 + g;
    const int r1 = r0 + 8;
    #pragma unroll
    for (int nt = 0; nt < 12; nt++) {
        int mat = nt >> 2;
        __half* dst = (mat == 0) ? g_k16 : (mat == 1) ? g_q16 : g_v16;
        int cm = (nt & 3) * 16 + 2 * tg;
        #pragma unroll
        for (int s = 0; s < 2; s++) {
            int col = cm + s * 8;
            *(u32*)&dst[(size_t)r0 * H_ + col] = pack_f16(c[nt][s][0], c[nt][s][1]);
            *(u32*)&dst[(size_t)r1 * H_ + col] = pack_f16(c[nt][s][2], c[nt][s][3]);
        }
    }
}

// ============================================================================
// Kernel 2: flash attention, all-fp16, KV-SPLIT x2 + 2 CTAs/SM (round-11 exact)
// ============================================================================
#define KROW 144
#define TILE_B (128 * KROW)        // 18432
#define BUF_B  (2 * TILE_B)        // k + v
#define ATTN_SMEM (2 * BUF_B)      // 73728 per CTA

__device__ __forceinline__ void stage_tile(u32 sb, int buf, int kbase, int tid)
{
    const u32 base = sb + buf * BUF_B;
    #pragma unroll
    for (int i = 0; i < 8; i++) {
        int idx = tid + i * 256;
        int arr = idx >> 10, j = idx & 1023;
        int r = j >> 3, ch = j & 7;
        const char* src = (const char*)(arr == 0 ? g_k16 : g_v16)
                        + ((size_t)(kbase + r) * H_ + ch * 8) * 2;
        CP16(base + arr * TILE_B + r * KROW + ch * 16, src);
    }
}

__global__ __launch_bounds__(256, 2) void attn_mma_kernel()
{
    extern __shared__ char smem[];
    const u32 sb = smem_u32(smem);

    const int tid = threadIdx.x;
    const int wid = tid >> 5;
    const int l   = tid & 31;
    const int g   = l >> 2;
    const int tg  = l & 3;

    const int split = blockIdx.x & 1;
    const int tile  = (blockIdx.x >> 1) & 15;
    const int b     = blockIdx.x >> 5;
    const int qbase  = b * T_ + tile * 128;
    const int kstart = b * T_ + split * (T_ / 2);
    const int r0 = qbase + wid * 16 + g;
    const int r1 = r0 + 8;

    u32 aQ[4][4];
    #pragma unroll
    for (int kk = 0; kk < 4; kk++) {
        int cb = kk * 16 + 2 * tg;
        aQ[kk][0] = *(const u32*)&g_q16[(size_t)r0 * H_ + cb];
        aQ[kk][1] = *(const u32*)&g_q16[(size_t)r1 * H_ + cb];
        aQ[kk][2] = *(const u32*)&g_q16[(size_t)r0 * H_ + cb + 8];
        aQ[kk][3] = *(const u32*)&g_q16[(size_t)r1 * H_ + cb + 8];
    }

    const u32 kRowOff = (u32)(((l & 7) + ((l >> 4) << 3)) * KROW + (((l >> 3) & 1) << 4));
    const u32 vRowOff = (u32)(((l & 7) + (((l >> 3) & 1) << 3)) * KROW + ((l >> 4) << 4));

    const u32 bOnes = (g == 0) ? 0x3C003C00u : 0u;

    float oc[8][4];
    #pragma unroll
    for (int i = 0; i < 8; i++)
        #pragma unroll
        for (int j = 0; j < 4; j++) oc[i][j] = 0.0f;
    float ocrs[4] = {0.0f, 0.0f, 0.0f, 0.0f};

    stage_tile(sb, 0, kstart, tid);
    CP_COMMIT();

    const int NT = (T_ / 2) / 128;   // 8
    for (int t = 0; t < NT; t++) {
        CP_WAIT0();
        __syncthreads();
        const int buf = t & 1;
        if (t + 1 < NT) {
            stage_tile(sb, buf ^ 1, kstart + (t + 1) * 128, tid);
            CP_COMMIT();
        }
        const u32 kh = sb + buf * BUF_B;
        const u32 vh = kh + TILE_B;

        #pragma unroll
        for (int kg = 0; kg < 8; kg++) {
            float s0[4] = {0.f, 0.f, 0.f, 0.f};
            float s1[4] = {0.f, 0.f, 0.f, 0.f};
            #pragma unroll
            for (int ks = 0; ks < 4; ks++) {
                u32 kb[4];
                ldm4(kb, kh + (u32)(kg * 16 * KROW + ks * 32) + kRowOff);
                mma4h(s0, aQ[ks], kb[0], kb[1]);
                mma4h(s1, aQ[ks], kb[2], kb[3]);
            }
            u32 ph[4];
            ph[0] = ex2h2(pack_f16(s0[0], s0[1]));
            ph[1] = ex2h2(pack_f16(s0[2], s0[3]));
            ph[2] = ex2h2(pack_f16(s1[0], s1[1]));
            ph[3] = ex2h2(pack_f16(s1[2], s1[3]));
            mma4h(ocrs, ph, bOnes, bOnes);
            #pragma unroll
            for (int np = 0; np < 4; np++) {
                u32 vb[4];
                ldm4t(vb, vh + (u32)(kg * 16 * KROW + np * 32) + vRowOff);
                mma4h(oc[2*np],   ph, vb[0], vb[1]);
                mma4h(oc[2*np+1], ph, vb[2], vb[3]);
            }
        }
    }

    // ---- epilogue: write unnormalized numerator + rowsum ----
    float* on = g_on + (size_t)split * (NROWS * H_);
    if (tg == 0) {
        g_rs[split * NROWS + r0] = ocrs[0];
        g_rs[split * NROWS + r1] = ocrs[2];
    }
    #pragma unroll
    for (int nt = 0; nt < 8; nt++) {
        int col = nt * 8 + 2 * tg;
        *(float2*)&on[(size_t)r0 * H_ + col] = make_float2(oc[nt][0], oc[nt][1]);
        *(float2*)&on[(size_t)r1 * H_ + col] = make_float2(oc[nt][2], oc[nt][3]);
    }
}

// ============================================================================
// Kernel 3: combine splits: out = (n0 + n1) / (r0 + r1)
// ============================================================================
__global__ void combine_kernel(float* __restrict__ out)
{
    int idx = blockIdx.x * 256 + threadIdx.x;        // float4 index, 262144 total
    int row = idx >> 4;                               // 16 float4 per row
    float inv = 1.0f / (g_rs[row] + g_rs[NROWS + row]);
    float4 a = ((const float4*)g_on)[idx];
    float4 c = ((const float4*)(g_on + (size_t)NROWS * H_))[idx];
    ((float4*)out)[idx] = make_float4((a.x + c.x) * inv, (a.y + c.y) * inv,
                                      (a.z + c.z) * inv, (a.w + c.w) * inv);
}

// ============================================================================
extern "C" void kernel_launch(void* const* d_in, const int* in_sizes, int n_in,
                              void* d_out, int out_size)
{
    const float* x  = (const float*)d_in[0];
    const float* Wk = (const float*)d_in[1];
    const float* Wq = (const float*)d_in[2];
    const float* Wv = (const float*)d_in[3];
    float* out = (float*)d_out;

    cudaFuncSetAttribute(qkv_mma_kernel,
                         cudaFuncAttributeMaxDynamicSharedMemorySize, QKV_SMEM);
    cudaFuncSetAttribute(attn_mma_kernel,
                         cudaFuncAttributeMaxDynamicSharedMemorySize, ATTN_SMEM);

    w_cvt_kernel<<<(C_ * 192 + 1023) / 1024, 256>>>(Wk, Wq, Wv);
    qkv_mma_kernel<<<NROWS / 128, 256, QKV_SMEM>>>(x);
    attn_mma_kernel<<<B_ * (T_ / 128) * 2, 256, ATTN_SMEM>>>();
    combine_kernel<<<NROWS * H_ / 4 / 256, 256>>>(out);
}